// round 11
// baseline (speedup 1.0000x reference)
#include <cuda_runtime.h>
#include <cuda_fp16.h>
#include <cstdint>
#include <cstddef>

// ---------------------------------------------------------------------------
// out = silu(x@Mg^T)*(x@Mu^T) @ Md^T, ternary-dequant octonion weights.
// Octonion structure collapses to j = i XOR k + sign LUT.
// R11: occupancy-3 GEMM. BM=128, BN=32/matrix dual, BK=64, 2-stage cp.async,
//      warp tile 32Mx16N per matrix (acc=32 floats), ~80 regs, 6 warps/SMSP.
// ---------------------------------------------------------------------------

static constexpr int MROWS = 4096, KD = 4096, NH = 10928, NH_PAD = 11008, K2 = 10944;
static constexpr int WN = 8 * 1366 * 512;

__device__ __half g_Mg[(size_t)NH_PAD * KD];
__device__ __half g_Mu[(size_t)NH_PAD * KD];
__device__ __half g_Md[(size_t)4096 * K2];
__device__ __half g_X [(size_t)MROWS * KD];
__device__ __half g_H [(size_t)MROWS * K2];
__device__ float  g_red[3 * 256];
__device__ float  g_scales[3];
__device__ float  g_inv[3];

// sign LUT: s[i*8+k] = S[i^k, i, k]
__constant__ float c_S[64] = {
 +1,+1,+1,+1,+1,+1,+1,+1,
 -1,+1,+1,-1,+1,-1,-1,+1,
 -1,-1,+1,+1,+1,+1,-1,-1,
 -1,+1,-1,+1,+1,-1,+1,-1,
 -1,-1,-1,-1,+1,+1,+1,+1,
 -1,+1,-1,+1,-1,+1,-1,+1,
 -1,+1,+1,-1,-1,+1,+1,-1,
 -1,-1,+1,+1,-1,-1,+1,+1};

// ---------------------------------------------------------------------------
// scales
// ---------------------------------------------------------------------------
__global__ void reduce_abs_kernel(const float* __restrict__ w0,
                                  const float* __restrict__ w1,
                                  const float* __restrict__ w2, int n) {
    int t = blockIdx.y;
    const float* w = (t == 0) ? w0 : (t == 1 ? w1 : w2);
    float s = 0.f;
    for (int i = blockIdx.x * blockDim.x + threadIdx.x; i < n;
         i += gridDim.x * blockDim.x)
        s += fabsf(w[i]);
    __shared__ float sh[256];
    sh[threadIdx.x] = s;
    __syncthreads();
    for (int st = 128; st > 0; st >>= 1) {
        if (threadIdx.x < st) sh[threadIdx.x] += sh[threadIdx.x + st];
        __syncthreads();
    }
    if (threadIdx.x == 0) g_red[t * 256 + blockIdx.x] = sh[0];
}

__global__ void finalize_scales_kernel(int n) {
    __shared__ float sh[256];
    for (int t = 0; t < 3; t++) {
        sh[threadIdx.x] = g_red[t * 256 + threadIdx.x];
        __syncthreads();
        for (int st = 128; st > 0; st >>= 1) {
            if (threadIdx.x < st) sh[threadIdx.x] += sh[threadIdx.x + st];
            __syncthreads();
        }
        if (threadIdx.x == 0) {
            float sc = sh[0] / (float)n;
            g_scales[t] = sc;
            g_inv[t]    = 1.0f / sc;
        }
        __syncthreads();
    }
}

// ---------------------------------------------------------------------------
// merged build: Mg, Mu, Md + x -> fp16
// ---------------------------------------------------------------------------
static constexpr int GU_ITEMS = NH * 512;
static constexpr int D_ITEMS  = 4096 * (K2 / 8);
static constexpr int X_ITEMS  = MROWS * KD / 8;

__global__ void build_all_kernel(__half* __restrict__ Mg, __half* __restrict__ Mu,
                                 __half* __restrict__ Md, __half* __restrict__ X,
                                 const float* __restrict__ wg,
                                 const float* __restrict__ wu,
                                 const float* __restrict__ wd,
                                 const float* __restrict__ x) {
    int id = blockIdx.x * blockDim.x + threadIdx.x;
    if (id < 2 * GU_ITEMS) {
        const float* W = (id < GU_ITEMS) ? wg : wu;
        __half* out    = (id < GU_ITEMS) ? Mg : Mu;
        float inv      = (id < GU_ITEMS) ? g_inv[0] : g_inv[1];
        int t  = (id < GU_ITEMS) ? id : id - GU_ITEMS;
        int r  = t >> 9;
        int c  = (t & 511) * 8;
        int k = r / 1366, o = r - k * 1366;
        int i = c >> 9, d = c & 511;
        int j = i ^ k;
        float sg = c_S[i * 8 + k];
        const float4* src = (const float4*)(W + ((size_t)(j * 1366 + o)) * 512 + d);
        float4 v0 = src[0], v1 = src[1];
        float q[8] = {v0.x, v0.y, v0.z, v0.w, v1.x, v1.y, v1.z, v1.w};
        __align__(16) __half h[8];
#pragma unroll
        for (int tt = 0; tt < 8; tt++) {
            float qq = rintf(q[tt] * inv);
            qq = fminf(1.f, fmaxf(-1.f, qq)) * sg;
            h[tt] = __float2half_rn(qq);
        }
        *(uint4*)(out + (size_t)r * 4096 + c) = *(uint4*)h;
        return;
    }
    int t = id - 2 * GU_ITEMS;
    if (t < D_ITEMS) {
        int r = t / (K2 / 8);
        int c = (t - r * (K2 / 8)) * 8;
        int k = r >> 9, o = r & 511;
        float inv = g_inv[2];
        int i = c / 1366, d = c - i * 1366;
        __align__(16) __half h[8];
#pragma unroll
        for (int tt = 0; tt < 8; tt++) {
            int cc = c + tt;
            if (cc < NH) {
                int j = i ^ k;
                float sg = c_S[i * 8 + k];
                float q = rintf(wd[((size_t)(j * 512 + o)) * 1366 + d] * inv);
                h[tt] = __float2half_rn(fminf(1.f, fmaxf(-1.f, q)) * sg);
            } else {
                h[tt] = __float2half_rn(0.f);
            }
            if (++d == 1366) { d = 0; ++i; }
        }
        *(uint4*)(Md + (size_t)r * K2 + c) = *(uint4*)h;
        return;
    }
    t -= D_ITEMS;
    if (t >= X_ITEMS) return;
    const float4* src = (const float4*)(x + (size_t)t * 8);
    float4 v0 = src[0], v1 = src[1];
    __align__(16) __half h[8];
    *(__half2*)(h + 0) = __floats2half2_rn(v0.x, v0.y);
    *(__half2*)(h + 2) = __floats2half2_rn(v0.z, v0.w);
    *(__half2*)(h + 4) = __floats2half2_rn(v1.x, v1.y);
    *(__half2*)(h + 6) = __floats2half2_rn(v1.z, v1.w);
    *(uint4*)(X + (size_t)t * 8) = *(uint4*)h;
}

// ---------------------------------------------------------------------------
// GEMM helpers
// ---------------------------------------------------------------------------
__device__ __forceinline__ uint32_t smem_u32(const void* p) {
    return (uint32_t)__cvta_generic_to_shared(p);
}
__device__ __forceinline__ void cp16(uint32_t s, const void* g) {
    asm volatile("cp.async.cg.shared.global [%0], [%1], 16;\n" :: "r"(s), "l"(g));
}
__device__ __forceinline__ void ldsm4(uint32_t& r0, uint32_t& r1, uint32_t& r2,
                                      uint32_t& r3, uint32_t addr) {
    asm volatile("ldmatrix.sync.aligned.m8n8.x4.shared.b16 {%0,%1,%2,%3}, [%4];"
                 : "=r"(r0), "=r"(r1), "=r"(r2), "=r"(r3) : "r"(addr));
}
__device__ __forceinline__ void mma16816(float c[4], const uint32_t a[4],
                                         const uint32_t b[2]) {
    asm("mma.sync.aligned.m16n8k16.row.col.f32.f16.f16.f32 "
        "{%0,%1,%2,%3}, {%4,%5,%6,%7}, {%8,%9}, {%0,%1,%2,%3};\n"
        : "+f"(c[0]), "+f"(c[1]), "+f"(c[2]), "+f"(c[3])
        : "r"(a[0]), "r"(a[1]), "r"(a[2]), "r"(a[3]), "r"(b[0]), "r"(b[1]));
}

// ---------------------------------------------------------------------------
// Dual-B HMMA GEMM, occupancy-3, 2-stage, transposed grid, K-phase rotated.
// Per CTA: A(128 x K) vs B0,B1 (32 x K each). Warp grid 4x2:
//   wm = warp>>1 (32 M rows), wn = warp&1 (16 N cols per matrix).
// EPI=0: B0=gate strip, B1=up strip -> silu(g)*u -> fp16 H (32 cols/CTA)
// EPI=1: B0,B1 = adjacent 32-row strips of Md -> fp32 out (64 cols/CTA)
// ---------------------------------------------------------------------------
template <int EPI>
__global__ void __launch_bounds__(256, 3)
hgemm(const __half* __restrict__ A, int lda,
      const __half* __restrict__ Bbase, int ldb,
      __half* __restrict__ Ch, float* __restrict__ Cf, int ldc,
      int Nvalid, int KT, int sbase,
      const __half* __restrict__ B1base) {
    extern __shared__ __align__(16) __half sm[];
    constexpr int LDA = 72;
    constexpr int A_T = 128 * LDA;          // halfs
    constexpr int B_T = 32 * LDA;
    constexpr int STG = A_T + 2 * B_T;      // 13824 halfs = 27648 B

    const int tid  = threadIdx.x;
    const int warp = tid >> 5, lane = tid & 31;
    const int wm = warp >> 1, wn = warp & 1;
    const int m0 = wm * 32, n0 = wn * 16;

    const int mt = blockIdx.x;          // M tile (fast)
    const int nt = blockIdx.y;          // N strip (slow)

    const int bid = mt + nt * gridDim.x;
    const int kt0 = (bid * 37) % KT;

    const __half* Ag = A + (size_t)mt * 128 * lda;
    const __half* Bg0;
    const __half* Bg1;
    if (EPI == 0) {
        Bg0 = Bbase  + (size_t)nt * 32 * ldb;
        Bg1 = B1base + (size_t)nt * 32 * ldb;
    } else {
        Bg0 = Bbase + (size_t)nt * 64 * ldb;
        Bg1 = Bg0 + (size_t)32 * ldb;
    }

    int a_row = m0 + (lane & 7) + ((lane >> 3) & 1) * 8;
    int a_col = (lane >> 4) * 8;
    int aoff[2];
#pragma unroll
    for (int mi = 0; mi < 2; mi++) aoff[mi] = (a_row + mi * 16) * LDA + a_col;
    int b_row = n0 + (lane & 7) + ((lane >> 4) & 1) * 8;
    int b_col = ((lane >> 3) & 1) * 8;
    const int boff = b_row * LDA + b_col;

    const uint32_t sb = smem_u32(sm);

    float acc0[2][2][4];
    float acc1[2][2][4];
#pragma unroll
    for (int a = 0; a < 2; a++)
#pragma unroll
        for (int b = 0; b < 2; b++)
#pragma unroll
            for (int e = 0; e < 4; e++) { acc0[a][b][e] = 0.f; acc1[a][b][e] = 0.f; }

    auto load_tile = [&](int kt_rot, int s) {
        uint32_t st = sb + (uint32_t)(s * STG) * 2;
        int k0 = kt_rot * 64;
#pragma unroll
        for (int u = 0; u < 4; u++) {            // A: 1024 chunks / 256 thr
            int id = u * 256 + tid;
            int row = id >> 3, ch = id & 7;
            cp16(st + row * (LDA * 2) + ch * 16,
                 Ag + (size_t)row * lda + k0 + ch * 8);
        }
        {                                        // B0: 256 chunks
            int row = tid >> 3, ch = tid & 7;
            cp16(st + A_T * 2 + row * (LDA * 2) + ch * 16,
                 Bg0 + (size_t)row * ldb + k0 + ch * 8);
            cp16(st + (A_T + B_T) * 2 + row * (LDA * 2) + ch * 16,
                 Bg1 + (size_t)row * ldb + k0 + ch * 8);
        }
        asm volatile("cp.async.commit_group;" ::: "memory");
    };

    auto rot = [&](int kt) { int r = kt0 + kt; if (r >= KT) r -= KT; return r; };

    load_tile(rot(0), 0);

    int stage = 0;
    for (int kt = 0; kt < KT; kt++) {
        asm volatile("cp.async.wait_group 0;" ::: "memory");
        __syncthreads();   // tile kt visible; all warps done with buffer stage^1

        if (kt + 1 < KT) load_tile(rot(kt + 1), stage ^ 1);

        uint32_t ab  = sb + (uint32_t)(stage * STG) * 2;
        uint32_t bb0 = ab + A_T * 2;
        uint32_t bb1 = ab + (A_T + B_T) * 2;

#pragma unroll
        for (int ksid = 0; ksid < 4; ksid++) {
            const int ks = ksid * 16;
            uint32_t af[2][4];
#pragma unroll
            for (int mi = 0; mi < 2; mi++)
                ldsm4(af[mi][0], af[mi][1], af[mi][2], af[mi][3],
                      ab + (uint32_t)(aoff[mi] + ks) * 2);
            uint32_t bf0[2][2], bf1[2][2];
            ldsm4(bf0[0][0], bf0[0][1], bf0[1][0], bf0[1][1],
                  bb0 + (uint32_t)(boff + ks) * 2);
            ldsm4(bf1[0][0], bf1[0][1], bf1[1][0], bf1[1][1],
                  bb1 + (uint32_t)(boff + ks) * 2);
#pragma unroll
            for (int mi = 0; mi < 2; mi++)
#pragma unroll
                for (int ni = 0; ni < 2; ni++) {
                    mma16816(acc0[mi][ni], af[mi], bf0[ni]);
                    mma16816(acc1[mi][ni], af[mi], bf1[ni]);
                }
        }
        stage ^= 1;
    }

    // epilogue
    const float s0 = g_scales[sbase];
    const float s1 = (EPI == 0) ? g_scales[sbase + 1] : s0;
    const int grp = lane >> 2, tig = lane & 3;

    if constexpr (EPI == 0) {
        const bool edge = ((nt + 1) * 32 > (unsigned)Nvalid);
#pragma unroll
        for (int mi = 0; mi < 2; mi++) {
#pragma unroll
            for (int ni = 0; ni < 2; ni++) {
                int rbase = mt * 128 + m0 + mi * 16 + grp;
                int cb    = nt * 32 + n0 + ni * 8 + tig * 2;
#pragma unroll
                for (int he = 0; he < 2; he++) {
                    int r = rbase + he * 8;
                    float g = acc0[mi][ni][he * 2 + 0] * s0;
                    float u = acc1[mi][ni][he * 2 + 0] * s1;
                    float h0 = u * (g / (1.f + __expf(-g)));
                    g = acc0[mi][ni][he * 2 + 1] * s0;
                    u = acc1[mi][ni][he * 2 + 1] * s1;
                    float h1 = u * (g / (1.f + __expf(-g)));
                    if (!edge || cb < Nvalid)
                        *(__half2*)(Ch + (size_t)r * ldc + cb) =
                            __floats2half2_rn(h0, h1);
                }
            }
        }
    } else {
#pragma unroll
        for (int mi = 0; mi < 2; mi++) {
#pragma unroll
            for (int ni = 0; ni < 2; ni++) {
                int rbase = mt * 128 + m0 + mi * 16 + grp;
                int cb0   = nt * 64 + n0 + ni * 8 + tig * 2;
#pragma unroll
                for (int he = 0; he < 2; he++) {
                    int r = rbase + he * 8;
                    float2 v0, v1;
                    v0.x = acc0[mi][ni][he * 2 + 0] * s0;
                    v0.y = acc0[mi][ni][he * 2 + 1] * s0;
                    v1.x = acc1[mi][ni][he * 2 + 0] * s0;
                    v1.y = acc1[mi][ni][he * 2 + 1] * s0;
                    *(float2*)(Cf + (size_t)r * ldc + cb0)      = v0;
                    *(float2*)(Cf + (size_t)r * ldc + cb0 + 32) = v1;
                }
            }
        }
    }
}

// ---------------------------------------------------------------------------
// launcher
// ---------------------------------------------------------------------------
extern "C" void kernel_launch(void* const* d_in, const int* in_sizes, int n_in,
                              void* d_out, int out_size) {
    (void)in_sizes; (void)n_in; (void)out_size;
    const float* x  = (const float*)d_in[0];
    const float* wg = (const float*)d_in[1];
    const float* wu = (const float*)d_in[2];
    const float* wd = (const float*)d_in[3];
    float* out = (float*)d_out;

    void* p;
    cudaGetSymbolAddress(&p, g_Mg); __half* Mg = (__half*)p;
    cudaGetSymbolAddress(&p, g_Mu); __half* Mu = (__half*)p;
    cudaGetSymbolAddress(&p, g_Md); __half* Md = (__half*)p;
    cudaGetSymbolAddress(&p, g_X);  __half* X  = (__half*)p;
    cudaGetSymbolAddress(&p, g_H);  __half* Hb = (__half*)p;

    reduce_abs_kernel<<<dim3(256, 3), 256>>>(wg, wu, wd, WN);
    finalize_scales_kernel<<<1, 256>>>(WN);

    int total_items = 2 * GU_ITEMS + D_ITEMS + X_ITEMS;
    build_all_kernel<<<(total_items + 255) / 256, 256>>>(
        Mg, Mu, Md, X, wg, wu, wd, x);

    constexpr int SMEM = 2 * (128 * 72 + 2 * 32 * 72) * (int)sizeof(__half); // 55296
    cudaFuncSetAttribute((const void*)hgemm<0>,
                         cudaFuncAttributeMaxDynamicSharedMemorySize, SMEM);
    cudaFuncSetAttribute((const void*)hgemm<1>,
                         cudaFuncAttributeMaxDynamicSharedMemorySize, SMEM);

    // fused gate+up -> H (fp16); N strips of 32; ceil(NH/32)=342 strips
    hgemm<0><<<dim3(MROWS / 128, (NH + 31) / 32), 256, SMEM>>>(
        X, KD, Mg, KD, Hb, nullptr, K2, NH, KD / 64, 0, Mu);

    // down (two 32-row strips of Md per CTA) -> out (fp32)
    hgemm<1><<<dim3(MROWS / 128, 4096 / 64), 256, SMEM>>>(
        Hb, K2, Md, K2, nullptr, out, 4096, 4096, K2 / 64, 2, nullptr);
}

// round 13
// speedup vs baseline: 1.1655x; 1.1655x over previous
#include <cuda_runtime.h>
#include <cuda_fp16.h>
#include <cstdint>
#include <cstddef>

// ---------------------------------------------------------------------------
// out = silu(x@Mg^T)*(x@Mu^T) @ Md^T, ternary-dequant octonion weights.
// Octonion structure collapses to j = i XOR k + sign LUT.
// R12: R10 config (occ-2, BM=128, BN=64 dual, BK=64, 3-stage, K-rotation)
//      with the CTA-wide __syncthreads mainloop replaced by a per-stage
//      mbarrier ring (full via cp.async.mbarrier.arrive.noinc, empty via
//      explicit arrives) so the co-saturated smem crossbar and tensor pipe
//      overlap instead of convoying.
// ---------------------------------------------------------------------------

static constexpr int MROWS = 4096, KD = 4096, NH = 10928, NH_PAD = 11008, K2 = 10944;
static constexpr int WN = 8 * 1366 * 512;

__device__ __half g_Mg[(size_t)NH_PAD * KD];
__device__ __half g_Mu[(size_t)NH_PAD * KD];
__device__ __half g_Md[(size_t)4096 * K2];
__device__ __half g_X [(size_t)MROWS * KD];
__device__ __half g_H [(size_t)MROWS * K2];
__device__ float  g_red[3 * 256];
__device__ float  g_scales[3];
__device__ float  g_inv[3];

// sign LUT: s[i*8+k] = S[i^k, i, k]
__constant__ float c_S[64] = {
 +1,+1,+1,+1,+1,+1,+1,+1,
 -1,+1,+1,-1,+1,-1,-1,+1,
 -1,-1,+1,+1,+1,+1,-1,-1,
 -1,+1,-1,+1,+1,-1,+1,-1,
 -1,-1,-1,-1,+1,+1,+1,+1,
 -1,+1,-1,+1,-1,+1,-1,+1,
 -1,+1,+1,-1,-1,+1,+1,-1,
 -1,-1,+1,+1,-1,-1,+1,+1};

// ---------------------------------------------------------------------------
// scales
// ---------------------------------------------------------------------------
__global__ void reduce_abs_kernel(const float* __restrict__ w0,
                                  const float* __restrict__ w1,
                                  const float* __restrict__ w2, int n) {
    int t = blockIdx.y;
    const float* w = (t == 0) ? w0 : (t == 1 ? w1 : w2);
    float s = 0.f;
    for (int i = blockIdx.x * blockDim.x + threadIdx.x; i < n;
         i += gridDim.x * blockDim.x)
        s += fabsf(w[i]);
    __shared__ float sh[256];
    sh[threadIdx.x] = s;
    __syncthreads();
    for (int st = 128; st > 0; st >>= 1) {
        if (threadIdx.x < st) sh[threadIdx.x] += sh[threadIdx.x + st];
        __syncthreads();
    }
    if (threadIdx.x == 0) g_red[t * 256 + blockIdx.x] = sh[0];
}

__global__ void finalize_scales_kernel(int n) {
    __shared__ float sh[256];
    for (int t = 0; t < 3; t++) {
        sh[threadIdx.x] = g_red[t * 256 + threadIdx.x];
        __syncthreads();
        for (int st = 128; st > 0; st >>= 1) {
            if (threadIdx.x < st) sh[threadIdx.x] += sh[threadIdx.x + st];
            __syncthreads();
        }
        if (threadIdx.x == 0) {
            float sc = sh[0] / (float)n;
            g_scales[t] = sc;
            g_inv[t]    = 1.0f / sc;
        }
        __syncthreads();
    }
}

// ---------------------------------------------------------------------------
// merged build: Mg, Mu, Md + x -> fp16
// ---------------------------------------------------------------------------
static constexpr int GU_ITEMS = NH * 512;
static constexpr int D_ITEMS  = 4096 * (K2 / 8);
static constexpr int X_ITEMS  = MROWS * KD / 8;

__global__ void build_all_kernel(__half* __restrict__ Mg, __half* __restrict__ Mu,
                                 __half* __restrict__ Md, __half* __restrict__ X,
                                 const float* __restrict__ wg,
                                 const float* __restrict__ wu,
                                 const float* __restrict__ wd,
                                 const float* __restrict__ x) {
    int id = blockIdx.x * blockDim.x + threadIdx.x;
    if (id < 2 * GU_ITEMS) {
        const float* W = (id < GU_ITEMS) ? wg : wu;
        __half* out    = (id < GU_ITEMS) ? Mg : Mu;
        float inv      = (id < GU_ITEMS) ? g_inv[0] : g_inv[1];
        int t  = (id < GU_ITEMS) ? id : id - GU_ITEMS;
        int r  = t >> 9;
        int c  = (t & 511) * 8;
        int k = r / 1366, o = r - k * 1366;
        int i = c >> 9, d = c & 511;
        int j = i ^ k;
        float sg = c_S[i * 8 + k];
        const float4* src = (const float4*)(W + ((size_t)(j * 1366 + o)) * 512 + d);
        float4 v0 = src[0], v1 = src[1];
        float q[8] = {v0.x, v0.y, v0.z, v0.w, v1.x, v1.y, v1.z, v1.w};
        __align__(16) __half h[8];
#pragma unroll
        for (int tt = 0; tt < 8; tt++) {
            float qq = rintf(q[tt] * inv);
            qq = fminf(1.f, fmaxf(-1.f, qq)) * sg;
            h[tt] = __float2half_rn(qq);
        }
        *(uint4*)(out + (size_t)r * 4096 + c) = *(uint4*)h;
        return;
    }
    int t = id - 2 * GU_ITEMS;
    if (t < D_ITEMS) {
        int r = t / (K2 / 8);
        int c = (t - r * (K2 / 8)) * 8;
        int k = r >> 9, o = r & 511;
        float inv = g_inv[2];
        int i = c / 1366, d = c - i * 1366;
        __align__(16) __half h[8];
#pragma unroll
        for (int tt = 0; tt < 8; tt++) {
            int cc = c + tt;
            if (cc < NH) {
                int j = i ^ k;
                float sg = c_S[i * 8 + k];
                float q = rintf(wd[((size_t)(j * 512 + o)) * 1366 + d] * inv);
                h[tt] = __float2half_rn(fminf(1.f, fmaxf(-1.f, q)) * sg);
            } else {
                h[tt] = __float2half_rn(0.f);
            }
            if (++d == 1366) { d = 0; ++i; }
        }
        *(uint4*)(Md + (size_t)r * K2 + c) = *(uint4*)h;
        return;
    }
    t -= D_ITEMS;
    if (t >= X_ITEMS) return;
    const float4* src = (const float4*)(x + (size_t)t * 8);
    float4 v0 = src[0], v1 = src[1];
    __align__(16) __half h[8];
    *(__half2*)(h + 0) = __floats2half2_rn(v0.x, v0.y);
    *(__half2*)(h + 2) = __floats2half2_rn(v0.z, v0.w);
    *(__half2*)(h + 4) = __floats2half2_rn(v1.x, v1.y);
    *(__half2*)(h + 6) = __floats2half2_rn(v1.z, v1.w);
    *(uint4*)(X + (size_t)t * 8) = *(uint4*)h;
}

// ---------------------------------------------------------------------------
// GEMM helpers
// ---------------------------------------------------------------------------
__device__ __forceinline__ uint32_t smem_u32(const void* p) {
    return (uint32_t)__cvta_generic_to_shared(p);
}
__device__ __forceinline__ void cp16(uint32_t s, const void* g) {
    asm volatile("cp.async.cg.shared.global [%0], [%1], 16;\n" :: "r"(s), "l"(g));
}
__device__ __forceinline__ void ldsm4(uint32_t& r0, uint32_t& r1, uint32_t& r2,
                                      uint32_t& r3, uint32_t addr) {
    asm volatile("ldmatrix.sync.aligned.m8n8.x4.shared.b16 {%0,%1,%2,%3}, [%4];"
                 : "=r"(r0), "=r"(r1), "=r"(r2), "=r"(r3) : "r"(addr));
}
__device__ __forceinline__ void mma16816(float c[4], const uint32_t a[4],
                                         const uint32_t b[2]) {
    asm("mma.sync.aligned.m16n8k16.row.col.f32.f16.f16.f32 "
        "{%0,%1,%2,%3}, {%4,%5,%6,%7}, {%8,%9}, {%0,%1,%2,%3};\n"
        : "+f"(c[0]), "+f"(c[1]), "+f"(c[2]), "+f"(c[3])
        : "r"(a[0]), "r"(a[1]), "r"(a[2]), "r"(a[3]), "r"(b[0]), "r"(b[1]));
}
__device__ __forceinline__ void mbar_init(uint32_t a, uint32_t cnt) {
    asm volatile("mbarrier.init.shared.b64 [%0], %1;" :: "r"(a), "r"(cnt) : "memory");
}
__device__ __forceinline__ void mbar_arrive(uint32_t a) {
    asm volatile("mbarrier.arrive.shared.b64 _, [%0];" :: "r"(a) : "memory");
}
__device__ __forceinline__ void cpasync_arrive_noinc(uint32_t a) {
    asm volatile("cp.async.mbarrier.arrive.noinc.shared.b64 [%0];" :: "r"(a) : "memory");
}
__device__ __forceinline__ void mbar_wait(uint32_t a, uint32_t ph) {
    asm volatile(
        "{\n\t.reg .pred P;\n\t"
        "WL_%=:\n\t"
        "mbarrier.try_wait.parity.acquire.cta.shared::cta.b64 P, [%0], %1, 0x989680;\n\t"
        "@P bra WD_%=;\n\t"
        "bra WL_%=;\n\t"
        "WD_%=:\n\t}"
        :: "r"(a), "r"(ph) : "memory");
}

// ---------------------------------------------------------------------------
// Dual-B HMMA GEMM, occ-2, transposed grid, K-rotation, mbarrier-ring sync.
// Per CTA: A(128 x K) vs B0,B1 (64 x K each). Warp tile 64M x 16N per matrix.
// EPI=0: B0=gate strip, B1=up strip -> silu(g)*u -> fp16 H (64 cols/CTA)
// EPI=1: B0,B1 = adjacent 64-row strips of Md -> fp32 out (128 cols/CTA)
// smem: [0,64) mbarriers (full[3] @0, empty[3] @24), tiles @64.
// ---------------------------------------------------------------------------
template <int EPI>
__global__ void __launch_bounds__(256, 2)
hgemm(const __half* __restrict__ A, int lda,
      const __half* __restrict__ Bbase, int ldb,
      __half* __restrict__ Ch, float* __restrict__ Cf, int ldc,
      int Nvalid, int KT, int sbase,
      const __half* __restrict__ B1base) {
    extern __shared__ __align__(16) __half sm[];
    constexpr int LDA = 72;
    constexpr int A_T = 128 * LDA;          // halfs
    constexpr int B_T = 64 * LDA;
    constexpr int STG = A_T + 2 * B_T;      // 18432 halfs = 36864 B

    const int tid  = threadIdx.x;
    const int warp = tid >> 5, lane = tid & 31;
    const int wm = warp >> 2, wn = warp & 3;
    const int m0 = wm * 64, n0 = wn * 16;

    const int mt = blockIdx.x;          // M tile (fast)
    const int nt = blockIdx.y;          // N strip (slow)

    const int bid = mt + nt * gridDim.x;
    const int kt0 = (bid * 37) % KT;

    const __half* Ag = A + (size_t)mt * 128 * lda;
    const __half* Bg0;
    const __half* Bg1;
    if (EPI == 0) {
        Bg0 = Bbase  + (size_t)nt * 64 * ldb;
        Bg1 = B1base + (size_t)nt * 64 * ldb;
    } else {
        Bg0 = Bbase + (size_t)nt * 128 * ldb;
        Bg1 = Bg0 + (size_t)64 * ldb;
    }

    int a_row = m0 + (lane & 7) + ((lane >> 3) & 1) * 8;
    int a_col = (lane >> 4) * 8;
    int aoff[4];
#pragma unroll
    for (int mi = 0; mi < 4; mi++) aoff[mi] = (a_row + mi * 16) * LDA + a_col;
    int b_row = n0 + (lane & 7) + ((lane >> 4) & 1) * 8;
    int b_col = ((lane >> 3) & 1) * 8;
    const int boff = b_row * LDA + b_col;

    const uint32_t sb = smem_u32(sm);
    const uint32_t mb_full  = sb;        // 3 x 8B
    const uint32_t mb_empty = sb + 24;   // 3 x 8B
    const uint32_t tiles    = sb + 64;

    if (tid == 0) {
#pragma unroll
        for (int s = 0; s < 3; s++) {
            mbar_init(mb_full  + s * 8, 256);
            mbar_init(mb_empty + s * 8, 256);
        }
    }
    __syncthreads();

    float acc0[4][2][4];
    float acc1[4][2][4];
#pragma unroll
    for (int a = 0; a < 4; a++)
#pragma unroll
        for (int b = 0; b < 2; b++)
#pragma unroll
            for (int e = 0; e < 4; e++) { acc0[a][b][e] = 0.f; acc1[a][b][e] = 0.f; }

    auto load_tile = [&](int kt_rot, int s) {
        uint32_t st = tiles + (uint32_t)(s * STG) * 2;
        int k0 = kt_rot * 64;
#pragma unroll
        for (int u = 0; u < 4; u++) {
            int id = u * 256 + tid;
            int row = id >> 3, ch = id & 7;
            cp16(st + row * (LDA * 2) + ch * 16,
                 Ag + (size_t)row * lda + k0 + ch * 8);
        }
#pragma unroll
        for (int u = 0; u < 2; u++) {
            int id = u * 256 + tid;
            int row = id >> 3, ch = id & 7;
            cp16(st + A_T * 2 + row * (LDA * 2) + ch * 16,
                 Bg0 + (size_t)row * ldb + k0 + ch * 8);
        }
#pragma unroll
        for (int u = 0; u < 2; u++) {
            int id = u * 256 + tid;
            int row = id >> 3, ch = id & 7;
            cp16(st + (A_T + B_T) * 2 + row * (LDA * 2) + ch * 16,
                 Bg1 + (size_t)row * ldb + k0 + ch * 8);
        }
    };

    auto rot = [&](int kt) { int r = kt0 + kt; if (r >= KT) r -= KT; return r; };

    // prologue: fill the 3-stage ring
    int npre = (KT < 3) ? KT : 3;
    for (int t = 0; t < npre; t++) {
        load_tile(rot(t), t);
        cpasync_arrive_noinc(mb_full + t * 8);
    }

    unsigned phbits = 0;   // per-stage parity, bit s
    int stage = 0;
    for (int kt = 0; kt < KT; kt++) {
        const uint32_t p = (phbits >> stage) & 1u;
        mbar_wait(mb_full + stage * 8, p);

        uint32_t ab  = tiles + (uint32_t)(stage * STG) * 2;
        uint32_t bb0 = ab + A_T * 2;
        uint32_t bb1 = ab + (A_T + B_T) * 2;

#pragma unroll
        for (int ksid = 0; ksid < 4; ksid++) {
            const int ks = ksid * 16;
            uint32_t af[4][4];
#pragma unroll
            for (int mi = 0; mi < 4; mi++)
                ldsm4(af[mi][0], af[mi][1], af[mi][2], af[mi][3],
                      ab + (uint32_t)(aoff[mi] + ks) * 2);
            uint32_t bf0[2][2], bf1[2][2];
            ldsm4(bf0[0][0], bf0[0][1], bf0[1][0], bf0[1][1],
                  bb0 + (uint32_t)(boff + ks) * 2);
            ldsm4(bf1[0][0], bf1[0][1], bf1[1][0], bf1[1][1],
                  bb1 + (uint32_t)(boff + ks) * 2);
#pragma unroll
            for (int mi = 0; mi < 4; mi++)
#pragma unroll
                for (int ni = 0; ni < 2; ni++) {
                    mma16816(acc0[mi][ni], af[mi], bf0[ni]);
                    mma16816(acc1[mi][ni], af[mi], bf1[ni]);
                }
        }

        mbar_arrive(mb_empty + stage * 8);
        if (kt + 3 < KT) {
            mbar_wait(mb_empty + stage * 8, p);   // all consumers done with stage
            load_tile(rot(kt + 3), stage);
            cpasync_arrive_noinc(mb_full + stage * 8);
        }
        phbits ^= (1u << stage);
        if (++stage == 3) stage = 0;
    }

    // epilogue
    const float s0 = g_scales[sbase];
    const float s1 = (EPI == 0) ? g_scales[sbase + 1] : s0;
    const int grp = lane >> 2, tig = lane & 3;

    if constexpr (EPI == 0) {
        const bool edge = ((nt + 1) * 64 > (unsigned)Nvalid);
#pragma unroll
        for (int mi = 0; mi < 4; mi++) {
#pragma unroll
            for (int ni = 0; ni < 2; ni++) {
                int rbase = mt * 128 + m0 + mi * 16 + grp;
                int cb    = nt * 64 + n0 + ni * 8 + tig * 2;
#pragma unroll
                for (int he = 0; he < 2; he++) {
                    int r = rbase + he * 8;
                    float g = acc0[mi][ni][he * 2 + 0] * s0;
                    float u = acc1[mi][ni][he * 2 + 0] * s1;
                    float h0 = u * (g / (1.f + __expf(-g)));
                    g = acc0[mi][ni][he * 2 + 1] * s0;
                    u = acc1[mi][ni][he * 2 + 1] * s1;
                    float h1 = u * (g / (1.f + __expf(-g)));
                    if (!edge || cb < Nvalid)
                        *(__half2*)(Ch + (size_t)r * ldc + cb) =
                            __floats2half2_rn(h0, h1);
                }
            }
        }
    } else {
#pragma unroll
        for (int mi = 0; mi < 4; mi++) {
#pragma unroll
            for (int ni = 0; ni < 2; ni++) {
                int rbase = mt * 128 + m0 + mi * 16 + grp;
                int cb0   = nt * 128 + n0 + ni * 8 + tig * 2;
#pragma unroll
                for (int he = 0; he < 2; he++) {
                    int r = rbase + he * 8;
                    float2 v0, v1;
                    v0.x = acc0[mi][ni][he * 2 + 0] * s0;
                    v0.y = acc0[mi][ni][he * 2 + 1] * s0;
                    v1.x = acc1[mi][ni][he * 2 + 0] * s0;
                    v1.y = acc1[mi][ni][he * 2 + 1] * s0;
                    *(float2*)(Cf + (size_t)r * ldc + cb0)      = v0;
                    *(float2*)(Cf + (size_t)r * ldc + cb0 + 64) = v1;
                }
            }
        }
    }
}

// ---------------------------------------------------------------------------
// launcher
// ---------------------------------------------------------------------------
extern "C" void kernel_launch(void* const* d_in, const int* in_sizes, int n_in,
                              void* d_out, int out_size) {
    (void)in_sizes; (void)n_in; (void)out_size;
    const float* x  = (const float*)d_in[0];
    const float* wg = (const float*)d_in[1];
    const float* wu = (const float*)d_in[2];
    const float* wd = (const float*)d_in[3];
    float* out = (float*)d_out;

    void* p;
    cudaGetSymbolAddress(&p, g_Mg); __half* Mg = (__half*)p;
    cudaGetSymbolAddress(&p, g_Mu); __half* Mu = (__half*)p;
    cudaGetSymbolAddress(&p, g_Md); __half* Md = (__half*)p;
    cudaGetSymbolAddress(&p, g_X);  __half* X  = (__half*)p;
    cudaGetSymbolAddress(&p, g_H);  __half* Hb = (__half*)p;

    reduce_abs_kernel<<<dim3(256, 3), 256>>>(wg, wu, wd, WN);
    finalize_scales_kernel<<<1, 256>>>(WN);

    int total_items = 2 * GU_ITEMS + D_ITEMS + X_ITEMS;
    build_all_kernel<<<(total_items + 255) / 256, 256>>>(
        Mg, Mu, Md, X, wg, wu, wd, x);

    constexpr int SMEM = 64 + 3 * (128 * 72 + 2 * 64 * 72) * (int)sizeof(__half);
    cudaFuncSetAttribute((const void*)hgemm<0>,
                         cudaFuncAttributeMaxDynamicSharedMemorySize, SMEM);
    cudaFuncSetAttribute((const void*)hgemm<1>,
                         cudaFuncAttributeMaxDynamicSharedMemorySize, SMEM);

    // fused gate+up -> H (fp16); grid: x = M tiles (fast), y = N strips
    hgemm<0><<<dim3(MROWS / 128, NH_PAD / 64), 256, SMEM>>>(
        X, KD, Mg, KD, Hb, nullptr, K2, NH, KD / 64, 0, Mu);

    // down -> out (fp32); grid: x = M tiles (fast), y = N strips
    hgemm<1><<<dim3(MROWS / 128, 4096 / 128), 256, SMEM>>>(
        Hb, K2, Md, K2, nullptr, out, 4096, 4096, K2 / 64, 2, nullptr);
}

// round 14
// speedup vs baseline: 1.3191x; 1.1318x over previous
#include <cuda_runtime.h>
#include <cuda_fp16.h>
#include <cstdint>
#include <cstddef>

// ---------------------------------------------------------------------------
// out = silu(x@Mg^T)*(x@Mu^T) @ Md^T, ternary-dequant octonion weights.
// Octonion structure collapses to j = i XOR k + sign LUT.
// R14: mbarrier-ring GEMM with load DISTANCE 2 (was 3): the reload target is
//      the buffer consumed one k-tile ago, so the empty-wait has one tile of
//      slack and leaves the critical path (R12/13 had a zero-slack rendezvous
//      hidden in the empty-wait).
// ---------------------------------------------------------------------------

static constexpr int MROWS = 4096, KD = 4096, NH = 10928, NH_PAD = 11008, K2 = 10944;
static constexpr int WN = 8 * 1366 * 512;

__device__ __half g_Mg[(size_t)NH_PAD * KD];
__device__ __half g_Mu[(size_t)NH_PAD * KD];
__device__ __half g_Md[(size_t)4096 * K2];
__device__ __half g_X [(size_t)MROWS * KD];
__device__ __half g_H [(size_t)MROWS * K2];
__device__ float  g_red[3 * 256];
__device__ float  g_scales[3];
__device__ float  g_inv[3];

// sign LUT: s[i*8+k] = S[i^k, i, k]
__constant__ float c_S[64] = {
 +1,+1,+1,+1,+1,+1,+1,+1,
 -1,+1,+1,-1,+1,-1,-1,+1,
 -1,-1,+1,+1,+1,+1,-1,-1,
 -1,+1,-1,+1,+1,-1,+1,-1,
 -1,-1,-1,-1,+1,+1,+1,+1,
 -1,+1,-1,+1,-1,+1,-1,+1,
 -1,+1,+1,-1,-1,+1,+1,-1,
 -1,-1,+1,+1,-1,-1,+1,+1};

// ---------------------------------------------------------------------------
// scales
// ---------------------------------------------------------------------------
__global__ void reduce_abs_kernel(const float* __restrict__ w0,
                                  const float* __restrict__ w1,
                                  const float* __restrict__ w2, int n) {
    int t = blockIdx.y;
    const float* w = (t == 0) ? w0 : (t == 1 ? w1 : w2);
    float s = 0.f;
    for (int i = blockIdx.x * blockDim.x + threadIdx.x; i < n;
         i += gridDim.x * blockDim.x)
        s += fabsf(w[i]);
    __shared__ float sh[256];
    sh[threadIdx.x] = s;
    __syncthreads();
    for (int st = 128; st > 0; st >>= 1) {
        if (threadIdx.x < st) sh[threadIdx.x] += sh[threadIdx.x + st];
        __syncthreads();
    }
    if (threadIdx.x == 0) g_red[t * 256 + blockIdx.x] = sh[0];
}

__global__ void finalize_scales_kernel(int n) {
    __shared__ float sh[256];
    for (int t = 0; t < 3; t++) {
        sh[threadIdx.x] = g_red[t * 256 + threadIdx.x];
        __syncthreads();
        for (int st = 128; st > 0; st >>= 1) {
            if (threadIdx.x < st) sh[threadIdx.x] += sh[threadIdx.x + st];
            __syncthreads();
        }
        if (threadIdx.x == 0) {
            float sc = sh[0] / (float)n;
            g_scales[t] = sc;
            g_inv[t]    = 1.0f / sc;
        }
        __syncthreads();
    }
}

// ---------------------------------------------------------------------------
// merged build: Mg, Mu, Md + x -> fp16
// ---------------------------------------------------------------------------
static constexpr int GU_ITEMS = NH * 512;
static constexpr int D_ITEMS  = 4096 * (K2 / 8);
static constexpr int X_ITEMS  = MROWS * KD / 8;

__global__ void build_all_kernel(__half* __restrict__ Mg, __half* __restrict__ Mu,
                                 __half* __restrict__ Md, __half* __restrict__ X,
                                 const float* __restrict__ wg,
                                 const float* __restrict__ wu,
                                 const float* __restrict__ wd,
                                 const float* __restrict__ x) {
    int id = blockIdx.x * blockDim.x + threadIdx.x;
    if (id < 2 * GU_ITEMS) {
        const float* W = (id < GU_ITEMS) ? wg : wu;
        __half* out    = (id < GU_ITEMS) ? Mg : Mu;
        float inv      = (id < GU_ITEMS) ? g_inv[0] : g_inv[1];
        int t  = (id < GU_ITEMS) ? id : id - GU_ITEMS;
        int r  = t >> 9;
        int c  = (t & 511) * 8;
        int k = r / 1366, o = r - k * 1366;
        int i = c >> 9, d = c & 511;
        int j = i ^ k;
        float sg = c_S[i * 8 + k];
        const float4* src = (const float4*)(W + ((size_t)(j * 1366 + o)) * 512 + d);
        float4 v0 = src[0], v1 = src[1];
        float q[8] = {v0.x, v0.y, v0.z, v0.w, v1.x, v1.y, v1.z, v1.w};
        __align__(16) __half h[8];
#pragma unroll
        for (int tt = 0; tt < 8; tt++) {
            float qq = rintf(q[tt] * inv);
            qq = fminf(1.f, fmaxf(-1.f, qq)) * sg;
            h[tt] = __float2half_rn(qq);
        }
        *(uint4*)(out + (size_t)r * 4096 + c) = *(uint4*)h;
        return;
    }
    int t = id - 2 * GU_ITEMS;
    if (t < D_ITEMS) {
        int r = t / (K2 / 8);
        int c = (t - r * (K2 / 8)) * 8;
        int k = r >> 9, o = r & 511;
        float inv = g_inv[2];
        int i = c / 1366, d = c - i * 1366;
        __align__(16) __half h[8];
#pragma unroll
        for (int tt = 0; tt < 8; tt++) {
            int cc = c + tt;
            if (cc < NH) {
                int j = i ^ k;
                float sg = c_S[i * 8 + k];
                float q = rintf(wd[((size_t)(j * 512 + o)) * 1366 + d] * inv);
                h[tt] = __float2half_rn(fminf(1.f, fmaxf(-1.f, q)) * sg);
            } else {
                h[tt] = __float2half_rn(0.f);
            }
            if (++d == 1366) { d = 0; ++i; }
        }
        *(uint4*)(Md + (size_t)r * K2 + c) = *(uint4*)h;
        return;
    }
    t -= D_ITEMS;
    if (t >= X_ITEMS) return;
    const float4* src = (const float4*)(x + (size_t)t * 8);
    float4 v0 = src[0], v1 = src[1];
    __align__(16) __half h[8];
    *(__half2*)(h + 0) = __floats2half2_rn(v0.x, v0.y);
    *(__half2*)(h + 2) = __floats2half2_rn(v0.z, v0.w);
    *(__half2*)(h + 4) = __floats2half2_rn(v1.x, v1.y);
    *(__half2*)(h + 6) = __floats2half2_rn(v1.z, v1.w);
    *(uint4*)(X + (size_t)t * 8) = *(uint4*)h;
}

// ---------------------------------------------------------------------------
// GEMM helpers
// ---------------------------------------------------------------------------
__device__ __forceinline__ uint32_t smem_u32(const void* p) {
    return (uint32_t)__cvta_generic_to_shared(p);
}
__device__ __forceinline__ void cp16(uint32_t s, const void* g) {
    asm volatile("cp.async.cg.shared.global [%0], [%1], 16;\n" :: "r"(s), "l"(g));
}
__device__ __forceinline__ void ldsm4(uint32_t& r0, uint32_t& r1, uint32_t& r2,
                                      uint32_t& r3, uint32_t addr) {
    asm volatile("ldmatrix.sync.aligned.m8n8.x4.shared.b16 {%0,%1,%2,%3}, [%4];"
                 : "=r"(r0), "=r"(r1), "=r"(r2), "=r"(r3) : "r"(addr));
}
__device__ __forceinline__ void mma16816(float c[4], const uint32_t a[4],
                                         const uint32_t b[2]) {
    asm("mma.sync.aligned.m16n8k16.row.col.f32.f16.f16.f32 "
        "{%0,%1,%2,%3}, {%4,%5,%6,%7}, {%8,%9}, {%0,%1,%2,%3};\n"
        : "+f"(c[0]), "+f"(c[1]), "+f"(c[2]), "+f"(c[3])
        : "r"(a[0]), "r"(a[1]), "r"(a[2]), "r"(a[3]), "r"(b[0]), "r"(b[1]));
}
__device__ __forceinline__ void mbar_init(uint32_t a, uint32_t cnt) {
    asm volatile("mbarrier.init.shared.b64 [%0], %1;" :: "r"(a), "r"(cnt) : "memory");
}
__device__ __forceinline__ void mbar_arrive(uint32_t a) {
    asm volatile("mbarrier.arrive.shared.b64 _, [%0];" :: "r"(a) : "memory");
}
__device__ __forceinline__ void cpasync_arrive_noinc(uint32_t a) {
    asm volatile("cp.async.mbarrier.arrive.noinc.shared.b64 [%0];" :: "r"(a) : "memory");
}
__device__ __forceinline__ void mbar_wait(uint32_t a, uint32_t ph) {
    asm volatile(
        "{\n\t.reg .pred P;\n\t"
        "WL_%=:\n\t"
        "mbarrier.try_wait.parity.acquire.cta.shared::cta.b64 P, [%0], %1, 0x989680;\n\t"
        "@P bra WD_%=;\n\t"
        "bra WL_%=;\n\t"
        "WD_%=:\n\t}"
        :: "r"(a), "r"(ph) : "memory");
}

// ---------------------------------------------------------------------------
// Dual-B HMMA GEMM, occ-2, transposed grid, K-rotation, mbarrier ring,
// load distance 2 (one-tile slack on the empty-wait).
// Per CTA: A(128 x K) vs B0,B1 (64 x K each). Warp tile 64M x 16N per matrix.
// EPI=0: B0=gate strip, B1=up strip -> silu(g)*u -> fp16 H (64 cols/CTA)
// EPI=1: B0,B1 = adjacent 64-row strips of Md -> fp32 out (128 cols/CTA)
// smem: [0,64) mbarriers (full[3] @0, empty[3] @24), tiles @64.
// ---------------------------------------------------------------------------
template <int EPI>
__global__ void __launch_bounds__(256, 2)
hgemm(const __half* __restrict__ A, int lda,
      const __half* __restrict__ Bbase, int ldb,
      __half* __restrict__ Ch, float* __restrict__ Cf, int ldc,
      int Nvalid, int KT, int sbase,
      const __half* __restrict__ B1base) {
    extern __shared__ __align__(16) __half sm[];
    constexpr int LDA = 72;
    constexpr int A_T = 128 * LDA;          // halfs
    constexpr int B_T = 64 * LDA;
    constexpr int STG = A_T + 2 * B_T;      // 18432 halfs = 36864 B

    const int tid  = threadIdx.x;
    const int warp = tid >> 5, lane = tid & 31;
    const int wm = warp >> 2, wn = warp & 3;
    const int m0 = wm * 64, n0 = wn * 16;

    const int mt = blockIdx.x;          // M tile (fast)
    const int nt = blockIdx.y;          // N strip (slow)

    const int bid = mt + nt * gridDim.x;
    const int kt0 = (bid * 37) % KT;

    const __half* Ag = A + (size_t)mt * 128 * lda;
    const __half* Bg0;
    const __half* Bg1;
    if (EPI == 0) {
        Bg0 = Bbase  + (size_t)nt * 64 * ldb;
        Bg1 = B1base + (size_t)nt * 64 * ldb;
    } else {
        Bg0 = Bbase + (size_t)nt * 128 * ldb;
        Bg1 = Bg0 + (size_t)64 * ldb;
    }

    int a_row = m0 + (lane & 7) + ((lane >> 3) & 1) * 8;
    int a_col = (lane >> 4) * 8;
    int aoff[4];
#pragma unroll
    for (int mi = 0; mi < 4; mi++) aoff[mi] = (a_row + mi * 16) * LDA + a_col;
    int b_row = n0 + (lane & 7) + ((lane >> 4) & 1) * 8;
    int b_col = ((lane >> 3) & 1) * 8;
    const int boff = b_row * LDA + b_col;

    const uint32_t sb = smem_u32(sm);
    const uint32_t mb_full  = sb;        // 3 x 8B
    const uint32_t mb_empty = sb + 24;   // 3 x 8B
    const uint32_t tiles    = sb + 64;

    if (tid == 0) {
#pragma unroll
        for (int s = 0; s < 3; s++) {
            mbar_init(mb_full  + s * 8, 256);
            mbar_init(mb_empty + s * 8, 256);
        }
    }
    __syncthreads();

    float acc0[4][2][4];
    float acc1[4][2][4];
#pragma unroll
    for (int a = 0; a < 4; a++)
#pragma unroll
        for (int b = 0; b < 2; b++)
#pragma unroll
            for (int e = 0; e < 4; e++) { acc0[a][b][e] = 0.f; acc1[a][b][e] = 0.f; }

    auto load_tile = [&](int kt_rot, int s) {
        uint32_t st = tiles + (uint32_t)(s * STG) * 2;
        int k0 = kt_rot * 64;
#pragma unroll
        for (int u = 0; u < 4; u++) {
            int id = u * 256 + tid;
            int row = id >> 3, ch = id & 7;
            cp16(st + row * (LDA * 2) + ch * 16,
                 Ag + (size_t)row * lda + k0 + ch * 8);
        }
#pragma unroll
        for (int u = 0; u < 2; u++) {
            int id = u * 256 + tid;
            int row = id >> 3, ch = id & 7;
            cp16(st + A_T * 2 + row * (LDA * 2) + ch * 16,
                 Bg0 + (size_t)row * ldb + k0 + ch * 8);
        }
#pragma unroll
        for (int u = 0; u < 2; u++) {
            int id = u * 256 + tid;
            int row = id >> 3, ch = id & 7;
            cp16(st + (A_T + B_T) * 2 + row * (LDA * 2) + ch * 16,
                 Bg1 + (size_t)row * ldb + k0 + ch * 8);
        }
    };

    auto rot = [&](int kt) { int r = kt0 + kt; if (r >= KT) r -= KT; return r; };

    // prologue: load 2 tiles ahead (distance 2)
    int npre = (KT < 2) ? KT : 2;
    for (int t = 0; t < npre; t++) {
        load_tile(rot(t), t);
        cpasync_arrive_noinc(mb_full + t * 8);
    }

    int cs = 0; unsigned cp_ = 0;   // consume stage / parity
    int ps = 2; unsigned pp = 0;    // produce stage / parity (of use index q)
    for (int kt = 0; kt < KT; kt++) {
        mbar_wait(mb_full + cs * 8, cp_);

        uint32_t ab  = tiles + (uint32_t)(cs * STG) * 2;
        uint32_t bb0 = ab + A_T * 2;
        uint32_t bb1 = ab + (A_T + B_T) * 2;

#pragma unroll
        for (int ksid = 0; ksid < 4; ksid++) {
            const int ks = ksid * 16;
            uint32_t af[4][4];
#pragma unroll
            for (int mi = 0; mi < 4; mi++)
                ldsm4(af[mi][0], af[mi][1], af[mi][2], af[mi][3],
                      ab + (uint32_t)(aoff[mi] + ks) * 2);
            uint32_t bf0[2][2], bf1[2][2];
            ldsm4(bf0[0][0], bf0[0][1], bf0[1][0], bf0[1][1],
                  bb0 + (uint32_t)(boff + ks) * 2);
            ldsm4(bf1[0][0], bf1[0][1], bf1[1][0], bf1[1][1],
                  bb1 + (uint32_t)(boff + ks) * 2);
#pragma unroll
            for (int mi = 0; mi < 4; mi++)
#pragma unroll
                for (int ni = 0; ni < 2; ni++) {
                    mma16816(acc0[mi][ni], af[mi], bf0[ni]);
                    mma16816(acc1[mi][ni], af[mi], bf1[ni]);
                }
        }

        mbar_arrive(mb_empty + cs * 8);

        if (kt + 2 < KT) {
            // target buffer ps was consumed at kt-1 -> one-tile slack
            if (kt >= 1) mbar_wait(mb_empty + ps * 8, pp ^ 1);
            load_tile(rot(kt + 2), ps);
            cpasync_arrive_noinc(mb_full + ps * 8);
            if (++ps == 3) { ps = 0; pp ^= 1; }
        }
        if (++cs == 3) { cs = 0; cp_ ^= 1; }
    }

    // epilogue
    const float s0 = g_scales[sbase];
    const float s1 = (EPI == 0) ? g_scales[sbase + 1] : s0;
    const int grp = lane >> 2, tig = lane & 3;

    if constexpr (EPI == 0) {
        const bool edge = ((nt + 1) * 64 > (unsigned)Nvalid);
#pragma unroll
        for (int mi = 0; mi < 4; mi++) {
#pragma unroll
            for (int ni = 0; ni < 2; ni++) {
                int rbase = mt * 128 + m0 + mi * 16 + grp;
                int cb    = nt * 64 + n0 + ni * 8 + tig * 2;
#pragma unroll
                for (int he = 0; he < 2; he++) {
                    int r = rbase + he * 8;
                    float g = acc0[mi][ni][he * 2 + 0] * s0;
                    float u = acc1[mi][ni][he * 2 + 0] * s1;
                    float h0 = u * (g / (1.f + __expf(-g)));
                    g = acc0[mi][ni][he * 2 + 1] * s0;
                    u = acc1[mi][ni][he * 2 + 1] * s1;
                    float h1 = u * (g / (1.f + __expf(-g)));
                    if (!edge || cb < Nvalid)
                        *(__half2*)(Ch + (size_t)r * ldc + cb) =
                            __floats2half2_rn(h0, h1);
                }
            }
        }
    } else {
#pragma unroll
        for (int mi = 0; mi < 4; mi++) {
#pragma unroll
            for (int ni = 0; ni < 2; ni++) {
                int rbase = mt * 128 + m0 + mi * 16 + grp;
                int cb0   = nt * 128 + n0 + ni * 8 + tig * 2;
#pragma unroll
                for (int he = 0; he < 2; he++) {
                    int r = rbase + he * 8;
                    float2 v0, v1;
                    v0.x = acc0[mi][ni][he * 2 + 0] * s0;
                    v0.y = acc0[mi][ni][he * 2 + 1] * s0;
                    v1.x = acc1[mi][ni][he * 2 + 0] * s0;
                    v1.y = acc1[mi][ni][he * 2 + 1] * s0;
                    *(float2*)(Cf + (size_t)r * ldc + cb0)      = v0;
                    *(float2*)(Cf + (size_t)r * ldc + cb0 + 64) = v1;
                }
            }
        }
    }
}

// ---------------------------------------------------------------------------
// launcher
// ---------------------------------------------------------------------------
extern "C" void kernel_launch(void* const* d_in, const int* in_sizes, int n_in,
                              void* d_out, int out_size) {
    (void)in_sizes; (void)n_in; (void)out_size;
    const float* x  = (const float*)d_in[0];
    const float* wg = (const float*)d_in[1];
    const float* wu = (const float*)d_in[2];
    const float* wd = (const float*)d_in[3];
    float* out = (float*)d_out;

    void* p;
    cudaGetSymbolAddress(&p, g_Mg); __half* Mg = (__half*)p;
    cudaGetSymbolAddress(&p, g_Mu); __half* Mu = (__half*)p;
    cudaGetSymbolAddress(&p, g_Md); __half* Md = (__half*)p;
    cudaGetSymbolAddress(&p, g_X);  __half* X  = (__half*)p;
    cudaGetSymbolAddress(&p, g_H);  __half* Hb = (__half*)p;

    reduce_abs_kernel<<<dim3(256, 3), 256>>>(wg, wu, wd, WN);
    finalize_scales_kernel<<<1, 256>>>(WN);

    int total_items = 2 * GU_ITEMS + D_ITEMS + X_ITEMS;
    build_all_kernel<<<(total_items + 255) / 256, 256>>>(
        Mg, Mu, Md, X, wg, wu, wd, x);

    constexpr int SMEM = 64 + 3 * (128 * 72 + 2 * 64 * 72) * (int)sizeof(__half);
    cudaFuncSetAttribute((const void*)hgemm<0>,
                         cudaFuncAttributeMaxDynamicSharedMemorySize, SMEM);
    cudaFuncSetAttribute((const void*)hgemm<1>,
                         cudaFuncAttributeMaxDynamicSharedMemorySize, SMEM);

    // fused gate+up -> H (fp16); grid: x = M tiles (fast), y = N strips
    hgemm<0><<<dim3(MROWS / 128, NH_PAD / 64), 256, SMEM>>>(
        X, KD, Mg, KD, Hb, nullptr, K2, NH, KD / 64, 0, Mu);

    // down -> out (fp32); grid: x = M tiles (fast), y = N strips
    hgemm<1><<<dim3(MROWS / 128, 4096 / 128), 256, SMEM>>>(
        Hb, K2, Md, K2, nullptr, out, 4096, 4096, K2 / 64, 2, nullptr);
}